// round 11
// baseline (speedup 1.0000x reference)
#include <cuda_runtime.h>
#include <math.h>

#define B_ 64
#define F_ 256
#define T_ 1024
#define H_ 1024
#define O_ 512

#define NB   256          // persistent blocks, 2 CTAs/SM co-resident
#define BT   16           // b rows per block
#define HTW  16           // h cols per block (8 interleaved pairs)
#define KC   128          // k chunk staged in smem (proven)
#define NCH  (H_ / KC)    // 8 chunks

#define WROWH (2 * H_ + 4)        // 2052 floats per h-pair row
#define SROW  (KC + 4)            // 132 floats
// smem: Wh 8*2052*4 = 65,664 B ; sS 2*16*132*4 = 16,896 B ; total 82,560 B
#define SMEM_RNN (8 * WROWH * 4 + 2 * BT * SROW * 4)

// Scratch: buf[t][b][h]. xb before step t, state s_t after (in place).
__device__ float g_buf[(size_t)T_ * B_ * H_];   // 256 MB
__device__ unsigned g_flags[NB];                // barrier arrival flags
__device__ unsigned g_rel2;                     // barrier release (monotonic)

// ---------------------------------------------------------------------------
// PROVEN R3 barrier (extended to 256 blocks): distributed arrival flags,
// leader (block 0) scans 2 flags/thread, single release word. Monotonic.
// ---------------------------------------------------------------------------
__device__ __forceinline__ void gsync(unsigned target) {
    __syncthreads();
    if (blockIdx.x == 0) {
        if (threadIdx.x == 0) {
            __threadfence();
            *(volatile unsigned*)&g_flags[0] = target;
        }
        unsigned i = threadIdx.x;       // 128 threads scan 256 flags
        while ((int)(*(volatile unsigned*)&g_flags[i] - target) < 0)
            __nanosleep(40);
        while ((int)(*(volatile unsigned*)&g_flags[i + 128] - target) < 0)
            __nanosleep(40);
        __syncthreads();
        if (threadIdx.x == 0) {
            __threadfence();
            *(volatile unsigned*)&g_rel2 = target;
        }
        __syncthreads();
    } else {
        if (threadIdx.x == 0) {
            __threadfence();            // order data before flag
            *(volatile unsigned*)&g_flags[blockIdx.x] = target;
            while ((int)(*(volatile unsigned*)&g_rel2 - target) < 0)
                __nanosleep(40);
            __threadfence();            // acquire + L1D refresh
        }
        __syncthreads();
    }
}

// ---- packed f32x2 helpers (sm_103a FFMA2 path; ptxas won't auto-fuse) ----
__device__ __forceinline__ unsigned long long pk2(float v) {
    unsigned long long r;
    asm("mov.b64 %0, {%1, %1};" : "=l"(r) : "f"(v));
    return r;
}
__device__ __forceinline__ void fma2(unsigned long long& a,
                                     unsigned long long x,
                                     unsigned long long y) {
    asm("fma.rn.f32x2 %0, %1, %2, %0;" : "+l"(a) : "l"(x), "l"(y));
}
__device__ __forceinline__ float2 unpk(unsigned long long v) {
    float2 f;
    asm("mov.b64 {%0, %1}, %2;" : "=f"(f.x), "=f"(f.y) : "l"(v));
    return f;
}

// ---------------------------------------------------------------------------
// Kernel 1: buf[t][b][h] = bias[h] + sum_f x[b][f][t] * Wx[f][h]
// Ping-pong smem, one __syncthreads per k-iter (measured ~950us).
// ---------------------------------------------------------------------------
__global__ __launch_bounds__(256) void k_xw(const float* __restrict__ x,
                                            const float* __restrict__ Wx,
                                            const float* __restrict__ bias) {
    const int BM = 128, BN = 128, BK = 8, NC = F_ / BK;
    __shared__ float As[2][BK][BM];
    __shared__ float Bs[2][BK][BN];

    int tid = threadIdx.x;
    int tx = tid % 16, ty = tid / 16;
    int n0 = blockIdx.x * BN;
    int mtile = blockIdx.y;
    int b  = mtile / (T_ / BM);
    int t0 = (mtile % (T_ / BM)) * BM;

    const float* xb = x + (size_t)b * F_ * T_ + t0;

    const int lk = tid >> 5;
    const int lq = (tid & 31) * 4;

    float4 ra = *reinterpret_cast<const float4*>(&xb[(size_t)lk * T_ + lq]);
    float4 rb = *reinterpret_cast<const float4*>(&Wx[(size_t)lk * H_ + n0 + lq]);
    *reinterpret_cast<float4*>(&As[0][lk][lq]) = ra;
    *reinterpret_cast<float4*>(&Bs[0][lk][lq]) = rb;
    __syncthreads();

    float acc[8][8];
#pragma unroll
    for (int i = 0; i < 8; i++)
#pragma unroll
        for (int j = 0; j < 8; j++) acc[i][j] = 0.f;

    for (int c = 0; c < NC; ++c) {
        int cur = c & 1;
        if (c + 1 < NC) {
            ra = *reinterpret_cast<const float4*>(
                &xb[(size_t)((c + 1) * BK + lk) * T_ + lq]);
            rb = *reinterpret_cast<const float4*>(
                &Wx[(size_t)((c + 1) * BK + lk) * H_ + n0 + lq]);
        }
#pragma unroll
        for (int k = 0; k < BK; k++) {
            float va[8], vb[8];
#pragma unroll
            for (int i = 0; i < 8; i++) va[i] = As[cur][k][ty + 16 * i];
#pragma unroll
            for (int j = 0; j < 8; j++) vb[j] = Bs[cur][k][tx + 16 * j];
#pragma unroll
            for (int i = 0; i < 8; i++)
#pragma unroll
                for (int j = 0; j < 8; j++) acc[i][j] += va[i] * vb[j];
        }
        if (c + 1 < NC) {
            *reinterpret_cast<float4*>(&As[1 - cur][lk][lq]) = ra;
            *reinterpret_cast<float4*>(&Bs[1 - cur][lk][lq]) = rb;
            __syncthreads();
        }
    }

#pragma unroll
    for (int i = 0; i < 8; i++) {
        int t = t0 + ty + 16 * i;
        float* dst = g_buf + ((size_t)t * B_ + b) * H_ + n0;
#pragma unroll
        for (int j = 0; j < 8; j++) {
            int n = tx + 16 * j;
            dst[n] = acc[i][j] + bias[n0 + n];
        }
    }
}

// ---------------------------------------------------------------------------
// Kernel 2: persistent recurrence, 256 blocks (2 CTAs/SM -> 2 warps/SMSP
// from INDEPENDENT CTAs: stalls of one overlap compute of the other).
// Block bx = (bt, ht): C[16 b][16 h], full K=1024. Wh slice resident in smem
// as interleaved (h, h+8) pairs (64 KB). 128 threads, 1b x 2h thread tile,
// R7 inner-loop idiom (LDS.128 + pk2 + fma.rn.f32x2). Leader barrier per step.
// ---------------------------------------------------------------------------
__global__ __launch_bounds__(128, 2) void k_rnn(const float* __restrict__ Wh) {
    extern __shared__ float smem[];
    float* sWh = smem;                      // [8][WROWH] interleaved pairs
    float* sS  = smem + 8 * WROWH;          // [2][BT][SROW]

    const int tid = threadIdx.x;
    const int bx  = blockIdx.x;
    const int bt  = bx >> 6;                // 0..3   (b group of 16)
    const int ht  = bx & 63;                // 0..63  (h tile of 16)
    const int b0  = bt * BT;
    const int h0  = ht * HTW;
    const int hp   = tid & 7;               // h pair: cols hp, hp+8
    const int brow = tid >> 3;              // 0..15, one b row

    // Load Wh slice once, pair-interleaved:
    // sWh[hh][2k+0] = Wh[k][h0+hh], sWh[hh][2k+1] = Wh[k][h0+hh+8]
    for (int i = tid; i < 8 * H_; i += 128) {
        int hh = i & 7;
        int k  = i >> 3;
        sWh[(size_t)hh * WROWH + 2 * k]     = Wh[(size_t)k * H_ + h0 + hh];
        sWh[(size_t)hh * WROWH + 2 * k + 1] = Wh[(size_t)k * H_ + h0 + hh + 8];
    }
    __syncthreads();

    const float* wRow = &sWh[(size_t)hp * WROWH];

    unsigned base = *(volatile unsigned*)&g_rel2;
    unsigned bar = 0;

    const int gb  = b0 + brow;
    const int gh0 = h0 + hp, gh1 = h0 + hp + 8;

    // prefetch xb for t = 0
    float xb0 = g_buf[(size_t)gb * H_ + gh0];
    float xb1 = g_buf[(size_t)gb * H_ + gh1];

    for (int t = 0; t < T_; ++t) {
        float* cur = g_buf + (size_t)t * B_ * H_;

        unsigned long long accA = 0ull;     // (out_h0, out_h1)

        if (t > 0) {
            const float* sp = g_buf + (size_t)(t - 1) * B_ * H_ + (size_t)b0 * H_;

            // preload chunk 0 (16 rows x 128 k = 512 float4 / 128 thr = 4 each)
            float4 pv[4];
#pragma unroll
            for (int it = 0; it < 4; it++) {
                int idx = it * 128 + tid;
                int row = idx >> 5, q = idx & 31;
                pv[it] = *reinterpret_cast<const float4*>(
                    &sp[(size_t)row * H_ + q * 4]);
            }

            for (int c = 0; c < NCH; ++c) {
                float* sb = sS + (c & 1) * (BT * SROW);
                __syncthreads();
#pragma unroll
                for (int it = 0; it < 4; it++) {
                    int idx = it * 128 + tid;
                    int row = idx >> 5, q = idx & 31;
                    *reinterpret_cast<float4*>(&sb[row * SROW + q * 4]) = pv[it];
                }
                __syncthreads();
                if (c + 1 < NCH) {
                    const float* spn = sp + (c + 1) * KC;
#pragma unroll
                    for (int it = 0; it < 4; it++) {
                        int idx = it * 128 + tid;
                        int row = idx >> 5, q = idx & 31;
                        pv[it] = *reinterpret_cast<const float4*>(
                            &spn[(size_t)row * H_ + q * 4]);
                    }
                }
                const float* sr = &sb[brow * SROW];
                const float* wr = wRow + c * (KC * 2);
#pragma unroll 8
                for (int q = 0; q < KC / 4; q++) {
                    float4 s = *reinterpret_cast<const float4*>(&sr[q * 4]);
                    ulonglong2 wa = *reinterpret_cast<const ulonglong2*>(&wr[q * 8]);
                    ulonglong2 wb = *reinterpret_cast<const ulonglong2*>(&wr[q * 8 + 4]);
                    fma2(accA, pk2(s.x), wa.x);
                    fma2(accA, pk2(s.y), wa.y);
                    fma2(accA, pk2(s.z), wb.x);
                    fma2(accA, pk2(s.w), wb.y);
                }
            }
        }

        // epilogue: s_t = tanh(xb + acc), in place
        float2 rA = unpk(accA);
        cur[(size_t)gb * H_ + gh0] = tanhf(xb0 + rA.x);
        cur[(size_t)gb * H_ + gh1] = tanhf(xb1 + rA.y);

        // prefetch next step's xb BEFORE the barrier (overlaps barrier wait)
        {
            const float* nxt = g_buf + (size_t)((t + 1 < T_) ? t + 1 : t) * B_ * H_;
            xb0 = nxt[(size_t)gb * H_ + gh0];
            xb1 = nxt[(size_t)gb * H_ + gh1];
        }

        gsync(base + (++bar));
    }
}

// ---------------------------------------------------------------------------
// Kernel 3: out[b][t][o] = bout[o] + sum_h buf[t][b][h] * Wout[h][o]
// Ping-pong smem, one __syncthreads per k-iter.
// ---------------------------------------------------------------------------
__global__ __launch_bounds__(256) void k_out(const float* __restrict__ Wout,
                                             const float* __restrict__ bout,
                                             float* __restrict__ out) {
    const int BM = 128, BN = 128, BK = 8, NC = H_ / BK;
    __shared__ float As[2][BK][BM + 4];
    __shared__ float Bs[2][BK][BN];

    int tid = threadIdx.x;
    int tx = tid % 16, ty = tid / 16;
    int n0 = blockIdx.x * BN;
    int m0 = blockIdx.y * BM;

    const float* A = g_buf;  // [m][k], m = t*B + b, K = H_

    const int mm = tid >> 1;
    const int kq = (tid & 1) * 4;
    const int lk = tid >> 5;
    const int lq = (tid & 31) * 4;

    float4 ra = *reinterpret_cast<const float4*>(&A[(size_t)(m0 + mm) * H_ + kq]);
    float4 rb = *reinterpret_cast<const float4*>(&Wout[(size_t)lk * O_ + n0 + lq]);
    As[0][kq + 0][mm] = ra.x;
    As[0][kq + 1][mm] = ra.y;
    As[0][kq + 2][mm] = ra.z;
    As[0][kq + 3][mm] = ra.w;
    *reinterpret_cast<float4*>(&Bs[0][lk][lq]) = rb;
    __syncthreads();

    float acc[8][8];
#pragma unroll
    for (int i = 0; i < 8; i++)
#pragma unroll
        for (int j = 0; j < 8; j++) acc[i][j] = 0.f;

    for (int c = 0; c < NC; ++c) {
        int cur = c & 1;
        if (c + 1 < NC) {
            ra = *reinterpret_cast<const float4*>(
                &A[(size_t)(m0 + mm) * H_ + (c + 1) * BK + kq]);
            rb = *reinterpret_cast<const float4*>(
                &Wout[(size_t)((c + 1) * BK + lk) * O_ + n0 + lq]);
        }
#pragma unroll
        for (int k = 0; k < BK; k++) {
            float va[8], vb[8];
#pragma unroll
            for (int i = 0; i < 8; i++) va[i] = As[cur][k][ty + 16 * i];
#pragma unroll
            for (int j = 0; j < 8; j++) vb[j] = Bs[cur][k][tx + 16 * j];
#pragma unroll
            for (int i = 0; i < 8; i++)
#pragma unroll
                for (int j = 0; j < 8; j++) acc[i][j] += va[i] * vb[j];
        }
        if (c + 1 < NC) {
            As[1 - cur][kq + 0][mm] = ra.x;
            As[1 - cur][kq + 1][mm] = ra.y;
            As[1 - cur][kq + 2][mm] = ra.z;
            As[1 - cur][kq + 3][mm] = ra.w;
            *reinterpret_cast<float4*>(&Bs[1 - cur][lk][lq]) = rb;
            __syncthreads();
        }
    }

    // m = t*B + b  ->  out[(b*T + t)*O + n]
#pragma unroll
    for (int i = 0; i < 8; i++) {
        int m = m0 + ty + 16 * i;
        int t = m >> 6;          // / B_
        int b = m & 63;          // % B_
        float* dst = out + ((size_t)b * T_ + t) * O_ + n0;
#pragma unroll
        for (int j = 0; j < 8; j++) {
            int n = tx + 16 * j;
            dst[n] = acc[i][j] + bout[n0 + n];
        }
    }
}

extern "C" void kernel_launch(void* const* d_in, const int* in_sizes, int n_in,
                              void* d_out, int out_size) {
    const float* x    = (const float*)d_in[0];
    const float* Wx   = (const float*)d_in[1];
    const float* Wh   = (const float*)d_in[2];
    const float* bias = (const float*)d_in[3];
    const float* Wout = (const float*)d_in[4];
    const float* bout = (const float*)d_in[5];
    float* out = (float*)d_out;

    (void)in_sizes; (void)n_in; (void)out_size;

    cudaFuncSetAttribute(k_rnn, cudaFuncAttributeMaxDynamicSharedMemorySize,
                         SMEM_RNN);

    dim3 g1(H_ / 128, (B_ * T_) / 128);   // (8, 512)
    k_xw<<<g1, 256>>>(x, Wx, bias);

    k_rnn<<<NB, 128, SMEM_RNN>>>(Wh);     // single persistent launch

    dim3 g3(O_ / 128, (B_ * T_) / 128);   // (4, 512)
    k_out<<<g3, 256>>>(Wout, bout, out);
}

// round 12
// speedup vs baseline: 1.4767x; 1.4767x over previous
#include <cuda_runtime.h>
#include <cuda_bf16.h>
#include <math.h>

#define B_ 64
#define F_ 256
#define T_ 1024
#define H_ 1024
#define O_ 512

#define NB   128          // persistent blocks
#define BT   16           // b rows per block
#define HT2  32           // h cols per block (stored as 16 interleaved pairs)
#define KC   128          // k chunk staged in smem (proven)
#define NCH  (H_ / KC)    // 8 chunks

#define WROW2 (2 * H_ + 4)        // 2052 floats: interleaved (h, h+16) pairs
#define SROW (KC + 4)             // 132 floats
#define SMEM_RNN ((16 * WROW2 + 2 * BT * SROW) * 4)

// Scratch: buf[t][b][h]. xb before step t, state s_t after (in place).
__device__ float g_buf[(size_t)T_ * B_ * H_];          // 256 MB
// bf16 split copies of the states, written by k_rnn epilogue: [t*B+b][h]
__device__ __nv_bfloat16 g_sh[(size_t)T_ * B_ * H_];   // 128 MB
__device__ __nv_bfloat16 g_sl[(size_t)T_ * B_ * H_];   // 128 MB
// bf16 split Wout
__device__ __nv_bfloat16 g_wh[H_ * O_];
__device__ __nv_bfloat16 g_wl[H_ * O_];
__device__ unsigned g_flags[NB];                // barrier arrival flags
__device__ unsigned g_rel2;                     // barrier release (monotonic)

// ---------------------------------------------------------------------------
// PROVEN R3/R7 barrier: distributed arrival flags, leader scans, one release.
// ---------------------------------------------------------------------------
__device__ __forceinline__ void gsync(unsigned target) {
    __syncthreads();
    if (blockIdx.x == 0) {
        if (threadIdx.x == 0) {
            __threadfence();
            *(volatile unsigned*)&g_flags[0] = target;
        }
        unsigned i = threadIdx.x;
        while ((int)(*(volatile unsigned*)&g_flags[i] - target) < 0)
            __nanosleep(40);
        __syncthreads();
        if (threadIdx.x == 0) {
            __threadfence();
            *(volatile unsigned*)&g_rel2 = target;
        }
        __syncthreads();
    } else {
        if (threadIdx.x == 0) {
            __threadfence();
            *(volatile unsigned*)&g_flags[blockIdx.x] = target;
            while ((int)(*(volatile unsigned*)&g_rel2 - target) < 0)
                __nanosleep(40);
            __threadfence();
        }
        __syncthreads();
    }
}

// ---- packed f32x2 helpers ----
__device__ __forceinline__ unsigned long long pk2(float v) {
    unsigned long long r;
    asm("mov.b64 %0, {%1, %1};" : "=l"(r) : "f"(v));
    return r;
}
__device__ __forceinline__ void fma2(unsigned long long& a,
                                     unsigned long long x,
                                     unsigned long long y) {
    asm("fma.rn.f32x2 %0, %1, %2, %0;" : "+l"(a) : "l"(x), "l"(y));
}
__device__ __forceinline__ float2 unpk(unsigned long long v) {
    float2 f;
    asm("mov.b64 {%0, %1}, %2;" : "=f"(f.x), "=f"(f.y) : "l"(v));
    return f;
}

// ---- mma helpers ----
__device__ __forceinline__ unsigned smem_u32(const void* p) {
    return (unsigned)__cvta_generic_to_shared(p);
}
__device__ __forceinline__ void ldsm4(unsigned* r, unsigned a) {
    asm volatile("ldmatrix.sync.aligned.m8n8.x4.shared.b16 {%0,%1,%2,%3}, [%4];"
        : "=r"(r[0]), "=r"(r[1]), "=r"(r[2]), "=r"(r[3]) : "r"(a));
}
__device__ __forceinline__ void ldsm4t(unsigned* r, unsigned a) {
    asm volatile("ldmatrix.sync.aligned.m8n8.x4.trans.shared.b16 {%0,%1,%2,%3}, [%4];"
        : "=r"(r[0]), "=r"(r[1]), "=r"(r[2]), "=r"(r[3]) : "r"(a));
}
__device__ __forceinline__ void mma16816(float* c, const unsigned* a,
                                         const unsigned* b) {
    asm volatile(
        "mma.sync.aligned.m16n8k16.row.col.f32.bf16.bf16.f32 "
        "{%0,%1,%2,%3}, {%4,%5,%6,%7}, {%8,%9}, {%0,%1,%2,%3};"
        : "+f"(c[0]), "+f"(c[1]), "+f"(c[2]), "+f"(c[3])
        : "r"(a[0]), "r"(a[1]), "r"(a[2]), "r"(a[3]), "r"(b[0]), "r"(b[1]));
}

// ---------------------------------------------------------------------------
// Kernel 0: one-shot Wout -> bf16 hi/lo split
// ---------------------------------------------------------------------------
__global__ void k_cvtW(const float* __restrict__ Wout) {
    int i = blockIdx.x * 256 + threadIdx.x;
    if (i < H_ * O_) {
        float v = Wout[i];
        __nv_bfloat16 h = __float2bfloat16(v);
        g_wh[i] = h;
        g_wl[i] = __float2bfloat16(v - __bfloat162float(h));
    }
}

// ---------------------------------------------------------------------------
// Kernel 1: buf[t][b][h] = bias[h] + sum_f x[b][f][t] * Wx[f][h]  (unchanged)
// ---------------------------------------------------------------------------
__global__ __launch_bounds__(256) void k_xw(const float* __restrict__ x,
                                            const float* __restrict__ Wx,
                                            const float* __restrict__ bias) {
    const int BM = 128, BN = 128, BK = 8, NC = F_ / BK;
    __shared__ float As[2][BK][BM];
    __shared__ float Bs[2][BK][BN];

    int tid = threadIdx.x;
    int tx = tid % 16, ty = tid / 16;
    int n0 = blockIdx.x * BN;
    int mtile = blockIdx.y;
    int b  = mtile / (T_ / BM);
    int t0 = (mtile % (T_ / BM)) * BM;

    const float* xb = x + (size_t)b * F_ * T_ + t0;

    const int lk = tid >> 5;
    const int lq = (tid & 31) * 4;

    float4 ra = *reinterpret_cast<const float4*>(&xb[(size_t)lk * T_ + lq]);
    float4 rb = *reinterpret_cast<const float4*>(&Wx[(size_t)lk * H_ + n0 + lq]);
    *reinterpret_cast<float4*>(&As[0][lk][lq]) = ra;
    *reinterpret_cast<float4*>(&Bs[0][lk][lq]) = rb;
    __syncthreads();

    float acc[8][8];
#pragma unroll
    for (int i = 0; i < 8; i++)
#pragma unroll
        for (int j = 0; j < 8; j++) acc[i][j] = 0.f;

    for (int c = 0; c < NC; ++c) {
        int cur = c & 1;
        if (c + 1 < NC) {
            ra = *reinterpret_cast<const float4*>(
                &xb[(size_t)((c + 1) * BK + lk) * T_ + lq]);
            rb = *reinterpret_cast<const float4*>(
                &Wx[(size_t)((c + 1) * BK + lk) * H_ + n0 + lq]);
        }
#pragma unroll
        for (int k = 0; k < BK; k++) {
            float va[8], vb[8];
#pragma unroll
            for (int i = 0; i < 8; i++) va[i] = As[cur][k][ty + 16 * i];
#pragma unroll
            for (int j = 0; j < 8; j++) vb[j] = Bs[cur][k][tx + 16 * j];
#pragma unroll
            for (int i = 0; i < 8; i++)
#pragma unroll
                for (int j = 0; j < 8; j++) acc[i][j] += va[i] * vb[j];
        }
        if (c + 1 < NC) {
            *reinterpret_cast<float4*>(&As[1 - cur][lk][lq]) = ra;
            *reinterpret_cast<float4*>(&Bs[1 - cur][lk][lq]) = rb;
            __syncthreads();
        }
    }

#pragma unroll
    for (int i = 0; i < 8; i++) {
        int t = t0 + ty + 16 * i;
        float* dst = g_buf + ((size_t)t * B_ + b) * H_ + n0;
#pragma unroll
        for (int j = 0; j < 8; j++) {
            int n = tx + 16 * j;
            dst[n] = acc[i][j] + bias[n0 + n];
        }
    }
}

// ---------------------------------------------------------------------------
// Kernel 2: persistent recurrence — EXACT R7 compute + barrier; epilogue
// additionally emits bf16 hi/lo copies of the state for the mma k_out.
// ---------------------------------------------------------------------------
__global__ __launch_bounds__(128, 1) void k_rnn(const float* __restrict__ Wh) {
    extern __shared__ float smem[];
    float* sWh = smem;                      // [16][WROW2] interleaved pairs
    float* sS  = smem + 16 * WROW2;         // [2][BT][SROW]

    const int tid = threadIdx.x;
    const int bx  = blockIdx.x;
    const int bt  = bx >> 5;
    const int ht  = bx & 31;
    const int b0  = bt * BT;
    const int h0  = ht * HT2;
    const int hIdx = tid & 15;
    const int bIdx = tid >> 4;

    for (int i = tid; i < 16 * H_; i += 128) {
        int hh = i & 15;
        int k  = i >> 4;
        sWh[(size_t)hh * WROW2 + 2 * k]     = Wh[(size_t)k * H_ + h0 + hh];
        sWh[(size_t)hh * WROW2 + 2 * k + 1] = Wh[(size_t)k * H_ + h0 + hh + 16];
    }
    __syncthreads();

    const float* wRow = &sWh[(size_t)hIdx * WROW2];

    unsigned base = *(volatile unsigned*)&g_rel2;
    unsigned bar = 0;

    const int gb0 = b0 + bIdx, gb1 = b0 + bIdx + 8;
    const int gh0 = h0 + hIdx, gh1 = h0 + hIdx + 16;

    float xb00 = g_buf[(size_t)gb0 * H_ + gh0];
    float xb01 = g_buf[(size_t)gb0 * H_ + gh1];
    float xb10 = g_buf[(size_t)gb1 * H_ + gh0];
    float xb11 = g_buf[(size_t)gb1 * H_ + gh1];

    for (int t = 0; t < T_; ++t) {
        float* cur = g_buf + (size_t)t * B_ * H_;

        unsigned long long accA = 0ull, accB = 0ull;

        if (t > 0) {
            const float* sp = g_buf + (size_t)(t - 1) * B_ * H_ + (size_t)b0 * H_;

            float4 pv[4];
#pragma unroll
            for (int it = 0; it < 4; it++) {
                int idx = it * 128 + tid;
                int row = idx >> 5, q = idx & 31;
                pv[it] = *reinterpret_cast<const float4*>(
                    &sp[(size_t)row * H_ + q * 4]);
            }

            for (int c = 0; c < NCH; ++c) {
                float* sb = sS + (c & 1) * (BT * SROW);
                __syncthreads();
#pragma unroll
                for (int it = 0; it < 4; it++) {
                    int idx = it * 128 + tid;
                    int row = idx >> 5, q = idx & 31;
                    *reinterpret_cast<float4*>(&sb[row * SROW + q * 4]) = pv[it];
                }
                __syncthreads();
                if (c + 1 < NCH) {
                    const float* spn = sp + (c + 1) * KC;
#pragma unroll
                    for (int it = 0; it < 4; it++) {
                        int idx = it * 128 + tid;
                        int row = idx >> 5, q = idx & 31;
                        pv[it] = *reinterpret_cast<const float4*>(
                            &spn[(size_t)row * H_ + q * 4]);
                    }
                }
                const float* s0r = &sb[bIdx * SROW];
                const float* s1r = &sb[(bIdx + 8) * SROW];
                const float* wr  = wRow + c * (KC * 2);
#pragma unroll 8
                for (int q = 0; q < KC / 4; q++) {
                    float4 s0 = *reinterpret_cast<const float4*>(&s0r[q * 4]);
                    float4 s1 = *reinterpret_cast<const float4*>(&s1r[q * 4]);
                    ulonglong2 wa = *reinterpret_cast<const ulonglong2*>(&wr[q * 8]);
                    ulonglong2 wb = *reinterpret_cast<const ulonglong2*>(&wr[q * 8 + 4]);
                    fma2(accA, pk2(s0.x), wa.x); fma2(accB, pk2(s1.x), wa.x);
                    fma2(accA, pk2(s0.y), wa.y); fma2(accB, pk2(s1.y), wa.y);
                    fma2(accA, pk2(s0.z), wb.x); fma2(accB, pk2(s1.z), wb.x);
                    fma2(accA, pk2(s0.w), wb.y); fma2(accB, pk2(s1.w), wb.y);
                }
            }
        }

        // epilogue: s_t = tanh(xb + acc), in place, plus bf16 hi/lo copies
        float2 rA = unpk(accA);
        float2 rB = unpk(accB);
        float s00 = tanhf(xb00 + rA.x);
        float s01 = tanhf(xb01 + rA.y);
        float s10 = tanhf(xb10 + rB.x);
        float s11 = tanhf(xb11 + rB.y);
        cur[(size_t)gb0 * H_ + gh0] = s00;
        cur[(size_t)gb0 * H_ + gh1] = s01;
        cur[(size_t)gb1 * H_ + gh0] = s10;
        cur[(size_t)gb1 * H_ + gh1] = s11;
        {
            size_t m0i = (size_t)(t * B_ + gb0) * H_;
            size_t m1i = (size_t)(t * B_ + gb1) * H_;
            __nv_bfloat16 h;
            h = __float2bfloat16(s00); g_sh[m0i + gh0] = h;
            g_sl[m0i + gh0] = __float2bfloat16(s00 - __bfloat162float(h));
            h = __float2bfloat16(s01); g_sh[m0i + gh1] = h;
            g_sl[m0i + gh1] = __float2bfloat16(s01 - __bfloat162float(h));
            h = __float2bfloat16(s10); g_sh[m1i + gh0] = h;
            g_sl[m1i + gh0] = __float2bfloat16(s10 - __bfloat162float(h));
            h = __float2bfloat16(s11); g_sh[m1i + gh1] = h;
            g_sl[m1i + gh1] = __float2bfloat16(s11 - __bfloat162float(h));
        }

        {
            const float* nxt = g_buf + (size_t)((t + 1 < T_) ? t + 1 : t) * B_ * H_;
            xb00 = nxt[(size_t)gb0 * H_ + gh0];
            xb01 = nxt[(size_t)gb0 * H_ + gh1];
            xb10 = nxt[(size_t)gb1 * H_ + gh0];
            xb11 = nxt[(size_t)gb1 * H_ + gh1];
        }

        gsync(base + (++bar));
    }
}

// ---------------------------------------------------------------------------
// Kernel 3: out = states @ Wout + bout via split-bf16 mma.sync.m16n8k16.
// D = Ah@Bh + Ah@Bl + Al@Bh, fp32 accum. Block tile 128x128, BK=32,
// 8 warps (4 m x 2 n), warp tile 32x64.
// ---------------------------------------------------------------------------
#define AST 40    // A smem row stride (bf16): 32 + 8 pad
#define BST 136   // B smem row stride (bf16): 128 + 8 pad

__global__ __launch_bounds__(256, 2) void k_out_mma(const float* __restrict__ bout,
                                                    float* __restrict__ out) {
    __shared__ __nv_bfloat16 Ah[128 * AST];
    __shared__ __nv_bfloat16 Al[128 * AST];
    __shared__ __nv_bfloat16 Bh[32 * BST];
    __shared__ __nv_bfloat16 Bl[32 * BST];

    const int tid  = threadIdx.x;
    const int lane = tid & 31;
    const int warp = tid >> 5;
    const int wy = warp & 3;          // m: 4 warps x 32
    const int wx = warp >> 2;         // n: 2 warps x 64
    const int mw = wy * 32;
    const int nw = wx * 64;
    const int n0 = blockIdx.x * 128;
    const int m0 = blockIdx.y * 128;

    const int lrow = lane & 15;
    const int lcol = (lane >> 4) << 3;

    float acc[2][8][4];
#pragma unroll
    for (int i = 0; i < 2; i++)
#pragma unroll
        for (int j = 0; j < 8; j++)
#pragma unroll
            for (int r = 0; r < 4; r++) acc[i][j][r] = 0.f;

    // staging thread mapping
    const int achunk = tid & 3,  arow = tid >> 2;    // A: 64 rows/pass
    const int bchunk = tid & 15, brow = tid >> 4;    // B: 16 rows/pass

    for (int kc = 0; kc < H_; kc += 32) {
        __syncthreads();
        // stage A hi/lo: rows m0..m0+127, k kc..kc+31
#pragma unroll
        for (int p = 0; p < 2; p++) {
            int row = arow + p * 64;
            size_t src = (size_t)(m0 + row) * H_ + kc + achunk * 8;
            *reinterpret_cast<uint4*>(&Ah[row * AST + achunk * 8]) =
                *reinterpret_cast<const uint4*>(&g_sh[src]);
            *reinterpret_cast<uint4*>(&Al[row * AST + achunk * 8]) =
                *reinterpret_cast<const uint4*>(&g_sl[src]);
        }
        // stage B hi/lo: rows k kc..kc+31, cols n0..n0+127
#pragma unroll
        for (int p = 0; p < 2; p++) {
            int row = brow + p * 16;
            size_t src = (size_t)(kc + row) * O_ + n0 + bchunk * 8;
            *reinterpret_cast<uint4*>(&Bh[row * BST + bchunk * 8]) =
                *reinterpret_cast<const uint4*>(&g_wh[src]);
            *reinterpret_cast<uint4*>(&Bl[row * BST + bchunk * 8]) =
                *reinterpret_cast<const uint4*>(&g_wl[src]);
        }
        __syncthreads();

#pragma unroll
        for (int kk = 0; kk < 2; kk++) {
            const int ks = kk * 16;
            unsigned ah[2][4], al[2][4];
#pragma unroll
            for (int fm = 0; fm < 2; fm++) {
                unsigned a1 = smem_u32(&Ah[(mw + fm * 16 + lrow) * AST + ks + lcol]);
                ldsm4(ah[fm], a1);
                unsigned a2 = smem_u32(&Al[(mw + fm * 16 + lrow) * AST + ks + lcol]);
                ldsm4(al[fm], a2);
            }
#pragma unroll
            for (int np = 0; np < 4; np++) {
                unsigned bh[4], bl[4];
                unsigned ba = smem_u32(&Bh[(ks + lrow) * BST + nw + np * 16 + lcol]);
                ldsm4t(bh, ba);
                unsigned bb = smem_u32(&Bl[(ks + lrow) * BST + nw + np * 16 + lcol]);
                ldsm4t(bl, bb);
#pragma unroll
                for (int half = 0; half < 2; half++) {
                    const int fn = np * 2 + half;
                    const unsigned* bhp = &bh[half * 2];
                    const unsigned* blp = &bl[half * 2];
                    mma16816(acc[0][fn], ah[0], bhp);
                    mma16816(acc[1][fn], ah[1], bhp);
                    mma16816(acc[0][fn], ah[0], blp);
                    mma16816(acc[1][fn], ah[1], blp);
                    mma16816(acc[0][fn], al[0], bhp);
                    mma16816(acc[1][fn], al[1], bhp);
                }
            }
        }
    }

    // epilogue: m = t*B + b -> out[(b*T + t)*O + n] + bout
    const int g  = lane >> 2;
    const int c2 = (lane & 3) * 2;
#pragma unroll
    for (int fm = 0; fm < 2; fm++) {
#pragma unroll
        for (int fn = 0; fn < 8; fn++) {
            int n = n0 + nw + fn * 8 + c2;
            float b0v = bout[n], b1v = bout[n + 1];
#pragma unroll
            for (int half = 0; half < 2; half++) {
                int m = m0 + mw + fm * 16 + g + half * 8;
                int t = m >> 6;
                int b = m & 63;
                float* dst = out + ((size_t)b * T_ + t) * O_ + n;
                dst[0] = acc[fm][fn][half * 2 + 0] + b0v;
                dst[1] = acc[fm][fn][half * 2 + 1] + b1v;
            }
        }
    }
}

extern "C" void kernel_launch(void* const* d_in, const int* in_sizes, int n_in,
                              void* d_out, int out_size) {
    const float* x    = (const float*)d_in[0];
    const float* Wx   = (const float*)d_in[1];
    const float* Wh   = (const float*)d_in[2];
    const float* bias = (const float*)d_in[3];
    const float* Wout = (const float*)d_in[4];
    const float* bout = (const float*)d_in[5];
    float* out = (float*)d_out;

    (void)in_sizes; (void)n_in; (void)out_size;

    cudaFuncSetAttribute(k_rnn, cudaFuncAttributeMaxDynamicSharedMemorySize,
                         SMEM_RNN);

    k_cvtW<<<(H_ * O_ + 255) / 256, 256>>>(Wout);

    dim3 g1(H_ / 128, (B_ * T_) / 128);   // (8, 512)
    k_xw<<<g1, 256>>>(x, Wx, bias);

    k_rnn<<<NB, 128, SMEM_RNN>>>(Wh);     // single persistent launch

    dim3 g3(O_ / 128, (B_ * T_) / 128);   // (4, 512)
    k_out_mma<<<g3, 256>>>(bout, out);
}

// round 13
// speedup vs baseline: 1.9839x; 1.3434x over previous
#include <cuda_runtime.h>
#include <cuda_bf16.h>
#include <math.h>

#define B_ 64
#define F_ 256
#define T_ 1024
#define H_ 1024
#define O_ 512

#define NB   128          // persistent blocks: 4 (bm) x 32 (ht)
#define KCH  256          // k chunk for s staging
#define NCHK 4            // chunks per step

// k_rnn smem layout (bf16 units)
#define WH_STRIDE 40                       // 32 cols + 8 pad
#define A_STRIDE  264                      // 256 k + 8 pad
#define OFF_WHH 0
#define OFF_WHL (1024 * WH_STRIDE)         // 40960
#define OFF_AH  (2 * 1024 * WH_STRIDE)     // 81920
#define A_BUF   (16 * A_STRIDE)            // 4224
#define OFF_AL  (OFF_AH + 2 * A_BUF)       // 90368
#define SMEM_RNN ((OFF_AL + 2 * A_BUF) * 2)  // 197,632 bytes

// xb buffer (written by k_xw, read-only for k_rnn): buf[t][b][h]
__device__ float g_buf[(size_t)T_ * B_ * H_];          // 256 MB
// bf16 hi/lo state copies: [t*B+b][h]  (the ONLY state representation now)
__device__ __nv_bfloat16 g_sh[(size_t)T_ * B_ * H_];   // 128 MB
__device__ __nv_bfloat16 g_sl[(size_t)T_ * B_ * H_];   // 128 MB
// bf16 split Wout
__device__ __nv_bfloat16 g_wh[H_ * O_];
__device__ __nv_bfloat16 g_wl[H_ * O_];
__device__ unsigned g_flags[NB];
__device__ unsigned g_rel2;

// ---------------------------------------------------------------------------
// PROVEN R3/R7 barrier: distributed arrival flags, leader scans, one release.
// ---------------------------------------------------------------------------
__device__ __forceinline__ void gsync(unsigned target) {
    __syncthreads();
    if (blockIdx.x == 0) {
        if (threadIdx.x == 0) {
            __threadfence();
            *(volatile unsigned*)&g_flags[0] = target;
        }
        unsigned i = threadIdx.x;
        while ((int)(*(volatile unsigned*)&g_flags[i] - target) < 0)
            __nanosleep(40);
        __syncthreads();
        if (threadIdx.x == 0) {
            __threadfence();
            *(volatile unsigned*)&g_rel2 = target;
        }
        __syncthreads();
    } else {
        if (threadIdx.x == 0) {
            __threadfence();
            *(volatile unsigned*)&g_flags[blockIdx.x] = target;
            while ((int)(*(volatile unsigned*)&g_rel2 - target) < 0)
                __nanosleep(40);
            __threadfence();
        }
        __syncthreads();
    }
}

// ---- mma helpers (proven in R11 k_out_mma) ----
__device__ __forceinline__ unsigned smem_u32(const void* p) {
    return (unsigned)__cvta_generic_to_shared(p);
}
__device__ __forceinline__ void ldsm4(unsigned* r, unsigned a) {
    asm volatile("ldmatrix.sync.aligned.m8n8.x4.shared.b16 {%0,%1,%2,%3}, [%4];"
        : "=r"(r[0]), "=r"(r[1]), "=r"(r[2]), "=r"(r[3]) : "r"(a));
}
__device__ __forceinline__ void ldsm4t(unsigned* r, unsigned a) {
    asm volatile("ldmatrix.sync.aligned.m8n8.x4.trans.shared.b16 {%0,%1,%2,%3}, [%4];"
        : "=r"(r[0]), "=r"(r[1]), "=r"(r[2]), "=r"(r[3]) : "r"(a));
}
__device__ __forceinline__ void mma16816(float* c, const unsigned* a,
                                         const unsigned* b) {
    asm volatile(
        "mma.sync.aligned.m16n8k16.row.col.f32.bf16.bf16.f32 "
        "{%0,%1,%2,%3}, {%4,%5,%6,%7}, {%8,%9}, {%0,%1,%2,%3};"
        : "+f"(c[0]), "+f"(c[1]), "+f"(c[2]), "+f"(c[3])
        : "r"(a[0]), "r"(a[1]), "r"(a[2]), "r"(a[3]), "r"(b[0]), "r"(b[1]));
}

// ---------------------------------------------------------------------------
// Kernel 0: one-shot Wout -> bf16 hi/lo split
// ---------------------------------------------------------------------------
__global__ void k_cvtW(const float* __restrict__ Wout) {
    int i = blockIdx.x * 256 + threadIdx.x;
    if (i < H_ * O_) {
        float v = Wout[i];
        __nv_bfloat16 h = __float2bfloat16(v);
        g_wh[i] = h;
        g_wl[i] = __float2bfloat16(v - __bfloat162float(h));
    }
}

// ---------------------------------------------------------------------------
// Kernel 1: buf[t][b][h] = bias[h] + sum_f x[b][f][t] * Wx[f][h]  (unchanged)
// ---------------------------------------------------------------------------
__global__ __launch_bounds__(256) void k_xw(const float* __restrict__ x,
                                            const float* __restrict__ Wx,
                                            const float* __restrict__ bias) {
    const int BM = 128, BN = 128, BK = 8, NC = F_ / BK;
    __shared__ float As[2][BK][BM];
    __shared__ float Bs[2][BK][BN];

    int tid = threadIdx.x;
    int tx = tid % 16, ty = tid / 16;
    int n0 = blockIdx.x * BN;
    int mtile = blockIdx.y;
    int b  = mtile / (T_ / BM);
    int t0 = (mtile % (T_ / BM)) * BM;

    const float* xb = x + (size_t)b * F_ * T_ + t0;

    const int lk = tid >> 5;
    const int lq = (tid & 31) * 4;

    float4 ra = *reinterpret_cast<const float4*>(&xb[(size_t)lk * T_ + lq]);
    float4 rb = *reinterpret_cast<const float4*>(&Wx[(size_t)lk * H_ + n0 + lq]);
    *reinterpret_cast<float4*>(&As[0][lk][lq]) = ra;
    *reinterpret_cast<float4*>(&Bs[0][lk][lq]) = rb;
    __syncthreads();

    float acc[8][8];
#pragma unroll
    for (int i = 0; i < 8; i++)
#pragma unroll
        for (int j = 0; j < 8; j++) acc[i][j] = 0.f;

    for (int c = 0; c < NC; ++c) {
        int cur = c & 1;
        if (c + 1 < NC) {
            ra = *reinterpret_cast<const float4*>(
                &xb[(size_t)((c + 1) * BK + lk) * T_ + lq]);
            rb = *reinterpret_cast<const float4*>(
                &Wx[(size_t)((c + 1) * BK + lk) * H_ + n0 + lq]);
        }
#pragma unroll
        for (int k = 0; k < BK; k++) {
            float va[8], vb[8];
#pragma unroll
            for (int i = 0; i < 8; i++) va[i] = As[cur][k][ty + 16 * i];
#pragma unroll
            for (int j = 0; j < 8; j++) vb[j] = Bs[cur][k][tx + 16 * j];
#pragma unroll
            for (int i = 0; i < 8; i++)
#pragma unroll
                for (int j = 0; j < 8; j++) acc[i][j] += va[i] * vb[j];
        }
        if (c + 1 < NC) {
            *reinterpret_cast<float4*>(&As[1 - cur][lk][lq]) = ra;
            *reinterpret_cast<float4*>(&Bs[1 - cur][lk][lq]) = rb;
            __syncthreads();
        }
    }

#pragma unroll
    for (int i = 0; i < 8; i++) {
        int t = t0 + ty + 16 * i;
        float* dst = g_buf + ((size_t)t * B_ + b) * H_ + n0;
#pragma unroll
        for (int j = 0; j < 8; j++) {
            int n = tx + 16 * j;
            dst[n] = acc[i][j] + bias[n0 + n];
        }
    }
}

// ---------------------------------------------------------------------------
// Kernel 2: persistent recurrence on TENSOR CORES (split-bf16 mma).
// Block bx = (bm, ht): C[16 b][32 h], full K=1024.
//   s_t = tanh(xb + s_{t-1}h @ Whh + s_{t-1}h @ Whl + s_{t-1}l @ Whh)
// Wh n-slice resident in smem as bf16 hi/lo (converted once). s_{t-1} hi/lo
// read from g_sh/g_sl (emitted by previous step's epilogue), staged per
// 256-k chunk, double-buffered. 4 warps, warp tile m16 x n8.
// Epilogue writes ONLY bf16 hi/lo state. R3 leader barrier per step.
// ---------------------------------------------------------------------------
__global__ __launch_bounds__(128, 1) void k_rnn(const float* __restrict__ Wh) {
    extern __shared__ __nv_bfloat16 sm[];
    __nv_bfloat16* whh = sm + OFF_WHH;    // [1024][WH_STRIDE]
    __nv_bfloat16* whl = sm + OFF_WHL;

    const int tid  = threadIdx.x;
    const int lane = tid & 31;
    const int warp = tid >> 5;
    const int bx = blockIdx.x;
    const int bm = bx >> 5;               // 0..3  (16 b rows)
    const int ht = bx & 31;               // 0..31 (32 h cols)
    const int b0 = bm * 16;
    const int n0 = ht * 32;

    // one-time: convert Wh[:, n0:n0+32] -> bf16 hi/lo in smem
    for (int idx = tid; idx < 1024 * 8; idx += 128) {
        int row = idx >> 3, q = (idx & 7) * 4;
        float4 v = *reinterpret_cast<const float4*>(
            &Wh[(size_t)row * H_ + n0 + q]);
        __nv_bfloat16* dh = &whh[row * WH_STRIDE + q];
        __nv_bfloat16* dl = &whl[row * WH_STRIDE + q];
        __nv_bfloat16 h;
        h = __float2bfloat16(v.x); dh[0] = h; dl[0] = __float2bfloat16(v.x - __bfloat162float(h));
        h = __float2bfloat16(v.y); dh[1] = h; dl[1] = __float2bfloat16(v.y - __bfloat162float(h));
        h = __float2bfloat16(v.z); dh[2] = h; dl[2] = __float2bfloat16(v.z - __bfloat162float(h));
        h = __float2bfloat16(v.w); dh[3] = h; dl[3] = __float2bfloat16(v.w - __bfloat162float(h));
    }
    __syncthreads();

    unsigned base = *(volatile unsigned*)&g_rel2;
    unsigned bar = 0;

    // mma fragment geometry
    const int lrow = lane & 15;
    const int lcol = (lane >> 4) << 3;
    const int r0 = lane >> 2;             // accum rows r0, r0+8
    const int c0 = (lane & 3) * 2;        // accum cols c0, c0+1
    const int hb = n0 + (warp >> 1) * 16 + (warp & 1) * 8;  // warp's n8 base
    const int gb0 = b0 + r0, gb1 = b0 + r0 + 8;
    const int gh  = hb + c0;

    // staging mapping: idx = it*128+tid -> row (0..15), k8 (0..31)
    // B ldsm column base for this warp (n16 region, half-selected)
    const int bcol = (warp >> 1) * 16 + lcol;

    // prefetch xb for t = 0
    float2 xbA = *reinterpret_cast<const float2*>(&g_buf[(size_t)gb0 * H_ + gh]);
    float2 xbB = *reinterpret_cast<const float2*>(&g_buf[(size_t)gb1 * H_ + gh]);

    for (int t = 0; t < T_; ++t) {
        float acc[4] = {0.f, 0.f, 0.f, 0.f};

        if (t > 0) {
            const __nv_bfloat16* sph = g_sh + ((size_t)(t - 1) * B_ + b0) * H_;
            const __nv_bfloat16* spl = g_sl + ((size_t)(t - 1) * B_ + b0) * H_;

            // preload chunk 0
            uint4 pvh[2], pvl[2];
#pragma unroll
            for (int it = 0; it < 2; it++) {
                int idx = it * 128 + tid;        // 256 slots = 16 rows x 16 k16s
                int row = idx >> 4, k16 = idx & 15;
                size_t src = (size_t)row * H_ + k16 * 16;
                pvh[it] = *reinterpret_cast<const uint4*>(&sph[src]);
                pvl[it] = *reinterpret_cast<const uint4*>(&spl[src]);
            }
            // NOTE: 16 rows x 256 k bf16 = 8192 elems = 512 x 16B; 128 thr x
            // 2 iters x (16B) covers 256 x 16B... use 16 bf16 (32B) per slot:
            // handled below with uint4 pairs (k16*16 elems = 32B = 2 uint4).
            // Simpler: each slot = 16 bf16 (32B): load as 2 uint4.
            // (pvh/pvl hold the first uint4; second loaded at STS time from L1)

            for (int c = 0; c < NCHK; ++c) {
                __nv_bfloat16* ah_s = sm + OFF_AH + (c & 1) * A_BUF;
                __nv_bfloat16* al_s = sm + OFF_AL + (c & 1) * A_BUF;
                __syncthreads();
#pragma unroll
                for (int it = 0; it < 2; it++) {
                    int idx = it * 128 + tid;
                    int row = idx >> 4, k16 = idx & 15;
                    size_t src = (size_t)row * H_ + c * KCH + k16 * 16;
                    // second half of the 32B slot (L1 hit: same line)
                    uint4 h2 = *reinterpret_cast<const uint4*>(&sph[src + 8]);
                    uint4 l2 = *reinterpret_cast<const uint4*>(&spl[src + 8]);
                    __nv_bfloat16* da = &ah_s[row * A_STRIDE + k16 * 16];
                    __nv_bfloat16* dl = &al_s[row * A_STRIDE + k16 * 16];
                    *reinterpret_cast<uint4*>(da)     = pvh[it];
                    *reinterpret_cast<uint4*>(da + 8) = h2;
                    *reinterpret_cast<uint4*>(dl)     = pvl[it];
                    *reinterpret_cast<uint4*>(dl + 8) = l2;
                }
                __syncthreads();
                if (c + 1 < NCHK) {
#pragma unroll
                    for (int it = 0; it < 2; it++) {
                        int idx = it * 128 + tid;
                        int row = idx >> 4, k16 = idx & 15;
                        size_t src = (size_t)row * H_ + (c + 1) * KCH + k16 * 16;
                        pvh[it] = *reinterpret_cast<const uint4*>(&sph[src]);
                        pvl[it] = *reinterpret_cast<const uint4*>(&spl[src]);
                    }
                }
                // compute chunk: 16 k16-steps
#pragma unroll 4
                for (int ks = 0; ks < KCH / 16; ks++) {
                    unsigned ah[4], al[4], bh[4], bl[4];
                    unsigned aA = smem_u32(&ah_s[lrow * A_STRIDE + ks * 16 + lcol]);
                    ldsm4(ah, aA);
                    unsigned aL = smem_u32(&al_s[lrow * A_STRIDE + ks * 16 + lcol]);
                    ldsm4(al, aL);
                    int kg = c * KCH + ks * 16;
                    unsigned bA = smem_u32(&whh[(kg + lrow) * WH_STRIDE + bcol]);
                    ldsm4t(bh, bA);
                    unsigned bL = smem_u32(&whl[(kg + lrow) * WH_STRIDE + bcol]);
                    ldsm4t(bl, bL);
                    const unsigned* bhp = &bh[(warp & 1) * 2];
                    const unsigned* blp = &bl[(warp & 1) * 2];
                    mma16816(acc, ah, bhp);
                    mma16816(acc, ah, blp);
                    mma16816(acc, al, bhp);
                }
            }
        }

        // epilogue: s_t = tanh(xb + acc); write bf16 hi/lo only
        {
            float s0x = tanhf(xbA.x + acc[0]);
            float s0y = tanhf(xbA.y + acc[1]);
            float s1x = tanhf(xbB.x + acc[2]);
            float s1y = tanhf(xbB.y + acc[3]);
            size_t m0i = ((size_t)t * B_ + gb0) * H_ + gh;
            size_t m1i = ((size_t)t * B_ + gb1) * H_ + gh;
            __nv_bfloat16 h0x = __float2bfloat16(s0x);
            __nv_bfloat16 h0y = __float2bfloat16(s0y);
            __nv_bfloat16 h1x = __float2bfloat16(s1x);
            __nv_bfloat16 h1y = __float2bfloat16(s1y);
            __nv_bfloat162 p;
            p.x = h0x; p.y = h0y;
            *reinterpret_cast<__nv_bfloat162*>(&g_sh[m0i]) = p;
            p.x = h1x; p.y = h1y;
            *reinterpret_cast<__nv_bfloat162*>(&g_sh[m1i]) = p;
            p.x = __float2bfloat16(s0x - __bfloat162float(h0x));
            p.y = __float2bfloat16(s0y - __bfloat162float(h0y));
            *reinterpret_cast<__nv_bfloat162*>(&g_sl[m0i]) = p;
            p.x = __float2bfloat16(s1x - __bfloat162float(h1x));
            p.y = __float2bfloat16(s1y - __bfloat162float(h1y));
            *reinterpret_cast<__nv_bfloat162*>(&g_sl[m1i]) = p;
        }

        // prefetch next step's xb BEFORE the barrier
        {
            const float* nxt = g_buf + (size_t)((t + 1 < T_) ? t + 1 : t) * B_ * H_;
            xbA = *reinterpret_cast<const float2*>(&nxt[(size_t)gb0 * H_ + gh]);
            xbB = *reinterpret_cast<const float2*>(&nxt[(size_t)gb1 * H_ + gh]);
        }

        gsync(base + (++bar));
    }
}

// ---------------------------------------------------------------------------
// Kernel 3: out = states @ Wout + bout via split-bf16 mma (proven, 576us).
// ---------------------------------------------------------------------------
#define AST 40
#define BST 136

__global__ __launch_bounds__(256, 2) void k_out_mma(const float* __restrict__ bout,
                                                    float* __restrict__ out) {
    __shared__ __nv_bfloat16 Ah[128 * AST];
    __shared__ __nv_bfloat16 Al[128 * AST];
    __shared__ __nv_bfloat16 Bh[32 * BST];
    __shared__ __nv_bfloat16 Bl[32 * BST];

    const int tid  = threadIdx.x;
    const int lane = tid & 31;
    const int warp = tid >> 5;
    const int wy = warp & 3;
    const int wx = warp >> 2;
    const int mw = wy * 32;
    const int nw = wx * 64;
    const int n0 = blockIdx.x * 128;
    const int m0 = blockIdx.y * 128;

    const int lrow = lane & 15;
    const int lcol = (lane >> 4) << 3;

    float acc[2][8][4];
#pragma unroll
    for (int i = 0; i < 2; i++)
#pragma unroll
        for (int j = 0; j < 8; j++)
#pragma unroll
            for (int r = 0; r < 4; r++) acc[i][j][r] = 0.f;

    const int achunk = tid & 3,  arow = tid >> 2;
    const int bchunk = tid & 15, brow = tid >> 4;

    for (int kc = 0; kc < H_; kc += 32) {
        __syncthreads();
#pragma unroll
        for (int p = 0; p < 2; p++) {
            int row = arow + p * 64;
            size_t src = (size_t)(m0 + row) * H_ + kc + achunk * 8;
            *reinterpret_cast<uint4*>(&Ah[row * AST + achunk * 8]) =
                *reinterpret_cast<const uint4*>(&g_sh[src]);
            *reinterpret_cast<uint4*>(&Al[row * AST + achunk * 8]) =
                *reinterpret_cast<const uint4*>(&g_sl[src]);
        }
#pragma unroll
        for (int p = 0; p < 2; p++) {
            int row = brow + p * 16;
            size_t src = (size_t)(kc + row) * O_ + n0 + bchunk * 8;
            *reinterpret_cast<uint4*>(&Bh[row * BST + bchunk * 8]) =
                *reinterpret_cast<const uint4*>(&g_wh[src]);
            *reinterpret_cast<uint4*>(&Bl[row * BST + bchunk * 8]) =
                *reinterpret_cast<const uint4*>(&g_wl[src]);
        }
        __syncthreads();

#pragma unroll
        for (int kk = 0; kk < 2; kk++) {
            const int ks = kk * 16;
            unsigned ah[2][4], al[2][4];
#pragma unroll
            for (int fm = 0; fm < 2; fm++) {
                unsigned a1 = smem_u32(&Ah[(mw + fm * 16 + lrow) * AST + ks + lcol]);
                ldsm4(ah[fm], a1);
                unsigned a2 = smem_u32(&Al[(mw + fm * 16 + lrow) * AST + ks + lcol]);
                ldsm4(al[fm], a2);
            }
#pragma unroll
            for (int np = 0; np < 4; np++) {
                unsigned bh[4], bl[4];
                unsigned ba = smem_u32(&Bh[(ks + lrow) * BST + nw + np * 16 + lcol]);
                ldsm4t(bh, ba);
                unsigned bb = smem_u32(&Bl[(ks + lrow) * BST + nw + np * 16 + lcol]);
                ldsm4t(bl, bb);
#pragma unroll
                for (int half = 0; half < 2; half++) {
                    const int fn = np * 2 + half;
                    const unsigned* bhp = &bh[half * 2];
                    const unsigned* blp = &bl[half * 2];
                    mma16816(acc[0][fn], ah[0], bhp);
                    mma16816(acc[1][fn], ah[1], bhp);
                    mma16816(acc[0][fn], ah[0], blp);
                    mma16816(acc[1][fn], ah[1], blp);
                    mma16816(acc[0][fn], al[0], bhp);
                    mma16816(acc[1][fn], al[1], bhp);
                }
            }
        }
    }

    const int g  = lane >> 2;
    const int c2 = (lane & 3) * 2;
#pragma unroll
    for (int fm = 0; fm < 2; fm++) {
#pragma unroll
        for (int fn = 0; fn < 8; fn++) {
            int n = n0 + nw + fn * 8 + c2;
            float b0v = bout[n], b1v = bout[n + 1];
#pragma unroll
            for (int half = 0; half < 2; half++) {
                int m = m0 + mw + fm * 16 + g + half * 8;
                int t = m >> 6;
                int b = m & 63;
                float* dst = out + ((size_t)b * T_ + t) * O_ + n;
                dst[0] = acc[fm][fn][half * 2 + 0] + b0v;
                dst[1] = acc[fm][fn][half * 2 + 1] + b1v;
            }
        }
    }
}

extern "C" void kernel_launch(void* const* d_in, const int* in_sizes, int n_in,
                              void* d_out, int out_size) {
    const float* x    = (const float*)d_in[0];
    const float* Wx   = (const float*)d_in[1];
    const float* Wh   = (const float*)d_in[2];
    const float* bias = (const float*)d_in[3];
    const float* Wout = (const float*)d_in[4];
    const float* bout = (const float*)d_in[5];
    float* out = (float*)d_out;

    (void)in_sizes; (void)n_in; (void)out_size;

    cudaFuncSetAttribute(k_rnn, cudaFuncAttributeMaxDynamicSharedMemorySize,
                         SMEM_RNN);

    k_cvtW<<<(H_ * O_ + 255) / 256, 256>>>(Wout);

    dim3 g1(H_ / 128, (B_ * T_) / 128);   // (8, 512)
    k_xw<<<g1, 256>>>(x, Wx, bias);

    k_rnn<<<NB, 128, SMEM_RNN>>>(Wh);     // single persistent launch

    dim3 g3(O_ / 128, (B_ * T_) / 128);   // (4, 512)
    k_out_mma<<<g3, 256>>>(bout, out);
}